// round 14
// baseline (speedup 1.0000x reference)
#include <cuda_runtime.h>
#include <cuda_fp16.h>
#include <cstdint>

#define IND       1024
#define ODIM      128
#define BATCHN    65536
#define BM        64
#define KC        64                  // k-elems per chunk (two 128B rows worth)
#define NITER     (IND / KC)          // 16
#define NTHR      256

#define PITCHB    144                 // bytes per fp16 smem row (+4 banks/row)
#define PITCHH    72
#define PANEL_H   (ODIM * PITCHH)     // 9216 halves per W k-panel (18432 B)
#define W_BYTES   18432

#define SM_MBAR     0                 // 2 mbarriers
#define SM_COEF     256
#define SM_SLOT     2048
#define TO_X        0
#define TO_Y        9216              // 64 rows x 144B
#define TO_W0       18432
#define TO_W1       36864
#define SLOT_BYTES  55296
#define W_TX        (2 * W_BYTES)
#define SMEM_TOTAL  (SM_SLOT + 2 * SLOT_BYTES)    // 112640 -> 2 CTAs/SM
#define EXP         132

typedef uint32_t U32;

// W normalized fp16 k64-panels: [kchunk][row][72 halves] (cols 64..71 zero)
__device__ __align__(1024) __half g_W0h[NITER * PANEL_H];
__device__ __align__(1024) __half g_W1h[NITER * PANEL_H];

// ---------------- PTX helpers ----------------

static __device__ __forceinline__ U32 s2u(const void* p) {
    U32 a;
    asm("{ .reg .u64 t; cvta.to.shared.u64 t, %1; cvt.u32.u64 %0, t; }" : "=r"(a) : "l"(p));
    return a;
}

static __device__ __forceinline__ void bulk_g2s(U32 dst, const void* src, U32 bytes, U32 mbar) {
    asm volatile("cp.async.bulk.shared::cluster.global.mbarrier::complete_tx::bytes "
                 "[%0], [%1], %2, [%3];"
                 :: "r"(dst), "l"(src), "r"(bytes), "r"(mbar) : "memory");
}

static __device__ __forceinline__ void mbar_init(U32 a, U32 cnt) {
    asm volatile("mbarrier.init.shared.b64 [%0], %1;" :: "r"(a), "r"(cnt) : "memory");
}
static __device__ __forceinline__ void mbar_expect(U32 a, U32 tx) {
    asm volatile("mbarrier.arrive.expect_tx.shared.b64 _, [%0], %1;" :: "r"(a), "r"(tx) : "memory");
}

#define MBAR_WAIT(addr, par) do {                                              \
    asm volatile("{\n\t.reg .pred P1;\n\t"                                     \
        "LAB_W_%=:\n\t"                                                        \
        "mbarrier.try_wait.parity.acquire.cta.shared::cta.b64 P1, [%0], %1, 0x989680;\n\t" \
        "@P1 bra.uni LAB_D_%=;\n\t"                                            \
        "bra.uni LAB_W_%=;\n\t"                                                \
        "LAB_D_%=:\n\t}"                                                       \
        :: "r"(addr), "r"(par) : "memory");                                    \
} while (0)

static __device__ __forceinline__ void ldsm4(U32& r0, U32& r1, U32& r2, U32& r3, U32 addr) {
    asm volatile("ldmatrix.sync.aligned.m8n8.x4.shared.b16 {%0,%1,%2,%3}, [%4];"
                 : "=r"(r0), "=r"(r1), "=r"(r2), "=r"(r3) : "r"(addr));
}

static __device__ __forceinline__ void mma16(float* c, U32 a0, U32 a1, U32 a2, U32 a3,
                                             U32 b0, U32 b1) {
    asm volatile("mma.sync.aligned.m16n8k16.row.col.f32.f16.f16.f32 "
                 "{%0,%1,%2,%3}, {%4,%5,%6,%7}, {%8,%9}, {%0,%1,%2,%3};"
                 : "+f"(c[0]), "+f"(c[1]), "+f"(c[2]), "+f"(c[3])
                 : "r"(a0), "r"(a1), "r"(a2), "r"(a3), "r"(b0), "r"(b1));
}

static __device__ __forceinline__ U32 cvt2h(float lo, float hi) {
    U32 r;
    asm("cvt.rn.f16x2.f32 %0, %1, %2;" : "=r"(r) : "f"(hi), "f"(lo));
    return r;
}

// ---------------- weight normalization + fp16 k64-panel packing ----------------
__global__ void normalize_kernel(const float* __restrict__ w) {
    int row  = blockIdx.x & (ODIM - 1);
    int half = blockIdx.x >> 7;
    const float* src = w + (size_t)row * (2 * IND) + (size_t)half * IND;
    __half* dst = half ? g_W1h : g_W0h;
    int t = threadIdx.x;  // 256 threads
    float v[4], s = 0.f, s2 = 0.f;
#pragma unroll
    for (int i = 0; i < 4; ++i) { v[i] = src[t + 256 * i]; s += v[i]; s2 += v[i] * v[i]; }
#pragma unroll
    for (int o = 16; o; o >>= 1) {
        s  += __shfl_xor_sync(~0u, s,  o);
        s2 += __shfl_xor_sync(~0u, s2, o);
    }
    __shared__ float sh[18];
    if ((t & 31) == 0) { sh[t >> 5] = s; sh[8 + (t >> 5)] = s2; }
    __syncthreads();
    if (t == 0) {
        float S = 0.f, S2 = 0.f;
#pragma unroll
        for (int i = 0; i < 8; ++i) { S += sh[i]; S2 += sh[8 + i]; }
        float mu = S * (1.f / IND);
        float ss = S2 - (float)IND * mu * mu;
        sh[16] = mu; sh[17] = rsqrtf(ss);
    }
    __syncthreads();
    float mu = sh[16], inv = sh[17];
#pragma unroll
    for (int i = 0; i < 4; ++i) {
        int k  = t + 256 * i;
        int kc = k >> 6, col = k & 63;
        dst[(size_t)kc * PANEL_H + row * PITCHH + col] = __float2half((v[i] - mu) * inv);
    }
    // zero pad cols 64..71 for all 16 panels of this row
    if (t < 128) {
        int kc = t >> 3, pc = 64 + (t & 7);
        dst[(size_t)kc * PANEL_H + row * PITCHH + pc] = __float2half(0.f);
    }
}

// ------------- main fused GEMM (fp16, KC=64, 16 iters, 2 CTAs/SM) ------------------
// 8 warps: warps 0-3: out0 = x*W0^T, warps 4-7: out1 = y*W1^T. Warp tile 32x64.
// x/y: 8x LDG.128 fp32 per thread per iter -> cvt after first k16 -> STS fp16.
// W: TMA bulk fp16 panels + mbarrier. One __syncthreads per iteration.

__global__ void __launch_bounds__(NTHR, 2)
gemm_kernel(const float* __restrict__ x, const float* __restrict__ y,
            const float* __restrict__ fc_bias, const float* __restrict__ a0,
            const float* __restrict__ a1, float* __restrict__ out) {
    extern __shared__ char smem[];
    const U32 sb = s2u(smem);
    const int tid = threadIdx.x;
    const int wid = tid >> 5, lid = tid & 31;
    const int m0 = blockIdx.x * BM;

    if (tid == 0) {
        mbar_init(sb + SM_MBAR + 0, 1);
        mbar_init(sb + SM_MBAR + 8, 1);
    }
    if (tid < 128) {
        float* sc = (float*)(smem + SM_COEF);
        sc[tid] = a0[tid]; sc[128 + tid] = a1[tid]; sc[256 + tid] = fc_bias[tid];
    }
    __syncthreads();

    // per-thread x/y load lanes: 16 chunks of 16B per 256B k-row segment
    const int ch = tid & 15;             // 16B chunk within the 256B (64-float) span
    const int r0 = tid >> 4;             // base row 0..15
    const float* px = x + (size_t)(m0 + r0) * IND + ch * 4;
    const float* py = y + (size_t)(m0 + r0) * IND + ch * 4;
    const size_t rstep = (size_t)16 * IND;
    U32 dA[4];
#pragma unroll
    for (int j = 0; j < 4; ++j)
        dA[j] = (U32)((r0 + 16 * j) * PITCHB + ch * 8);

    // prologue: chunks 0,1 -> slots 0,1 (direct), W TMA for both
    if (tid == 0) {
        mbar_expect(sb + SM_MBAR + 0, W_TX);
        bulk_g2s(sb + SM_SLOT + TO_W0, g_W0h, W_BYTES, sb + SM_MBAR + 0);
        bulk_g2s(sb + SM_SLOT + TO_W1, g_W1h, W_BYTES, sb + SM_MBAR + 0);
        mbar_expect(sb + SM_MBAR + 8, W_TX);
        bulk_g2s(sb + SM_SLOT + SLOT_BYTES + TO_W0, g_W0h + PANEL_H, W_BYTES, sb + SM_MBAR + 8);
        bulk_g2s(sb + SM_SLOT + SLOT_BYTES + TO_W1, g_W1h + PANEL_H, W_BYTES, sb + SM_MBAR + 8);
    }
#pragma unroll
    for (int s = 0; s < 2; ++s) {
        const U32 st = sb + SM_SLOT + (U32)(s * SLOT_BYTES);
#pragma unroll
        for (int j = 0; j < 4; ++j) {
            float4 xv = *(const float4*)(px + s * KC + j * rstep);
            float4 yv = *(const float4*)(py + s * KC + j * rstep);
            U32 h0 = cvt2h(xv.x, xv.y), h1 = cvt2h(xv.z, xv.w);
            asm volatile("st.shared.v2.b32 [%0], {%1,%2};" :: "r"(st + TO_X + dA[j]), "r"(h0), "r"(h1));
            h0 = cvt2h(yv.x, yv.y); h1 = cvt2h(yv.z, yv.w);
            asm volatile("st.shared.v2.b32 [%0], {%1,%2};" :: "r"(st + TO_Y + dA[j]), "r"(h0), "r"(h1));
        }
    }
    const float* plx = px + 2 * KC;
    const float* ply = py + 2 * KC;
    MBAR_WAIT(sb + SM_MBAR + 0, 0u);
    __syncthreads();                     // slot 0 fully ready

    // warp role
    const int g1 = wid >> 2;             // 0: GEMM0 (x,W0), 1: GEMM1 (y,W1)
    const int wl = wid & 3;
    const int mw = wl & 1;               // m-half (32 rows)
    const int nw = wl >> 1;              // n-half (64 cols)

    const int sel  = lid >> 3;
    const int lrow = lid & 7;
    const int aRowL = (sel & 1) * 8 + lrow;
    const U32 aKb   = (U32)((sel >> 1) * 16);
    const int bRowL = sel * 8 + lrow;

    U32 aOff[2];
#pragma unroll
    for (int mt = 0; mt < 2; ++mt)
        aOff[mt] = (U32)((mw * 32 + mt * 16 + aRowL) * PITCHB) + aKb;
    U32 bOff[2];
#pragma unroll
    for (int g = 0; g < 2; ++g)
        bOff[g] = (U32)((nw * 64 + g * 32 + bRowL) * PITCHB);

    float acc[2][8][4];
#pragma unroll
    for (int mt = 0; mt < 2; ++mt)
#pragma unroll
        for (int nt = 0; nt < 8; ++nt)
#pragma unroll
            for (int q = 0; q < 4; ++q) acc[mt][nt][q] = 0.f;

    const U32 toA = g1 ? TO_Y : TO_X;
    const U32 toB = g1 ? TO_W1 : TO_W0;

    int ph0 = 1, ph1 = 0;
    for (int i = 0; i < NITER; ++i) {
        const int s = i & 1;
        const bool more = (i + 2 < NITER);

        // issue LDG batch for chunk i+2 (in flight across first k16 block)
        float4 xv[4], yv[4];
        if (more) {
#pragma unroll
            for (int j = 0; j < 4; ++j) {
                xv[j] = *(const float4*)(plx + j * rstep);
                yv[j] = *(const float4*)(ply + j * rstep);
            }
            plx += KC; ply += KC;
        }

        const U32 st = sb + SM_SLOT + (U32)(s * SLOT_BYTES);
        const U32 abase = st + toA;
        const U32 bbase = st + toB;

        U32 hx[8], hy[8];
#pragma unroll
        for (int ks = 0; ks < 4; ++ks) {       // 4 k16-steps per 64-elem chunk
            const U32 kb = (U32)(ks * 32);
            U32 a[2][4];
#pragma unroll
            for (int mt = 0; mt < 2; ++mt)
                ldsm4(a[mt][0], a[mt][1], a[mt][2], a[mt][3], abase + aOff[mt] + kb);
#pragma unroll
            for (int g = 0; g < 2; ++g) {
                U32 b0[4], b1[4];
                ldsm4(b0[0], b0[1], b0[2], b0[3], bbase + bOff[g] + kb);
                ldsm4(b1[0], b1[1], b1[2], b1[3], bbase + bOff[g] + kb + 16u);
#pragma unroll
                for (int mt = 0; mt < 2; ++mt)
#pragma unroll
                    for (int j = 0; j < 4; ++j)
                        mma16(acc[mt][4 * g + j], a[mt][0], a[mt][1], a[mt][2], a[mt][3],
                              b0[j], b1[j]);
            }
            if (ks == 0 && more) {
                // convert in-flight fp32 to fp16x2 regs (frees the float4s)
#pragma unroll
                for (int j = 0; j < 4; ++j) {
                    hx[2 * j]     = cvt2h(xv[j].x, xv[j].y);
                    hx[2 * j + 1] = cvt2h(xv[j].z, xv[j].w);
                    hy[2 * j]     = cvt2h(yv[j].x, yv[j].y);
                    hy[2 * j + 1] = cvt2h(yv[j].z, yv[j].w);
                }
            }
        }

        if (i + 1 < NITER) {
            if (s) { MBAR_WAIT(sb + SM_MBAR + 0, (U32)ph0); ph0 ^= 1; }
            else   { MBAR_WAIT(sb + SM_MBAR + 8, (U32)ph1); ph1 ^= 1; }
            __syncthreads();                   // slot s free; slot s^1 ready
            if (more) {
#pragma unroll
                for (int j = 0; j < 4; ++j) {
                    asm volatile("st.shared.v2.b32 [%0], {%1,%2};"
                                 :: "r"(st + TO_X + dA[j]), "r"(hx[2 * j]), "r"(hx[2 * j + 1]));
                    asm volatile("st.shared.v2.b32 [%0], {%1,%2};"
                                 :: "r"(st + TO_Y + dA[j]), "r"(hy[2 * j]), "r"(hy[2 * j + 1]));
                }
                if (tid == 0) {
                    const U32 mb = sb + SM_MBAR + s * 8;
                    mbar_expect(mb, W_TX);
                    bulk_g2s(st + TO_W0, g_W0h + (size_t)(i + 2) * PANEL_H, W_BYTES, mb);
                    bulk_g2s(st + TO_W1, g_W1h + (size_t)(i + 2) * PANEL_H, W_BYTES, mb);
                }
            }
        }
    }
    __syncthreads();

    // ---------- epilogue ----------
    float* exch = (float*)(smem + SM_SLOT);    // reuse slot area: 64 x EXP fp32
    const float* sa0 = (const float*)(smem + SM_COEF);
    const float* sa1 = sa0 + 128;
    const float* sbs = sa0 + 256;

    const int rowb = mw * 32 + (lid >> 2);
    const int colb = nw * 64 + 2 * (lid & 3);

    if (!g1) {
#pragma unroll
        for (int mt = 0; mt < 2; ++mt) {
            const int rl = rowb + mt * 16;
#pragma unroll
            for (int nt = 0; nt < 8; ++nt) {
                const int c = colb + nt * 8;
                float2 v0 = make_float2(acc[mt][nt][0], acc[mt][nt][1]);
                float2 v1 = make_float2(acc[mt][nt][2], acc[mt][nt][3]);
                *(float2*)(out + (size_t)(m0 + rl)     * ODIM + c) = v0;
                *(float2*)(out + (size_t)(m0 + rl + 8) * ODIM + c) = v1;
                *(float2*)(exch + rl * EXP + c)       = v0;
                *(float2*)(exch + (rl + 8) * EXP + c) = v1;
            }
        }
    } else {
        float* o1 = out + (size_t)BATCHN * ODIM;
#pragma unroll
        for (int mt = 0; mt < 2; ++mt) {
            const int rl = rowb + mt * 16;
#pragma unroll
            for (int nt = 0; nt < 8; ++nt) {
                const int c = colb + nt * 8;
                *(float2*)(o1 + (size_t)(m0 + rl)     * ODIM + c) =
                    make_float2(acc[mt][nt][0], acc[mt][nt][1]);
                *(float2*)(o1 + (size_t)(m0 + rl + 8) * ODIM + c) =
                    make_float2(acc[mt][nt][2], acc[mt][nt][3]);
            }
        }
    }
    __syncthreads();

    if (g1) {
        float* o2 = out + 2 * (size_t)BATCHN * ODIM;
#pragma unroll
        for (int mt = 0; mt < 2; ++mt) {
            const int rl = rowb + mt * 16;
#pragma unroll
            for (int nt = 0; nt < 8; ++nt) {
                const int c = colb + nt * 8;
                float2 p0 = *(const float2*)(exch + rl * EXP + c);
                float2 p1 = *(const float2*)(exch + (rl + 8) * EXP + c);
                const float A0x = sa0[c], A0y = sa0[c + 1];
                const float A1x = sa1[c], A1y = sa1[c + 1];
                const float Bx  = sbs[c], By  = sbs[c + 1];
                float2 r0, r1;
                r0.x = p0.x * A0x + acc[mt][nt][0] * A1x + Bx;
                r0.y = p0.y * A0y + acc[mt][nt][1] * A1y + By;
                r1.x = p1.x * A0x + acc[mt][nt][2] * A1x + Bx;
                r1.y = p1.y * A0y + acc[mt][nt][3] * A1y + By;
                *(float2*)(o2 + (size_t)(m0 + rl)     * ODIM + c) = r0;
                *(float2*)(o2 + (size_t)(m0 + rl + 8) * ODIM + c) = r1;
            }
        }
    }
}

// ---------------- launch ----------------

extern "C" void kernel_launch(void* const* d_in, const int* in_sizes, int n_in,
                              void* d_out, int out_size) {
    const float* x  = (const float*)d_in[0];
    const float* y  = (const float*)d_in[1];
    const float* fw = (const float*)d_in[2];
    const float* fb = (const float*)d_in[3];
    const float* a0 = (const float*)d_in[4];
    const float* a1 = (const float*)d_in[5];
    float* out = (float*)d_out;

    normalize_kernel<<<2 * ODIM, 256>>>(fw);

    cudaFuncSetAttribute(gemm_kernel, cudaFuncAttributeMaxDynamicSharedMemorySize, SMEM_TOTAL);
    gemm_kernel<<<BATCHN / BM, NTHR, SMEM_TOTAL>>>(x, y, fb, a0, a1, out);
}

// round 15
// speedup vs baseline: 1.3860x; 1.3860x over previous
#include <cuda_runtime.h>
#include <cuda_fp16.h>
#include <cstdint>

#define IND       1024
#define ODIM      128
#define BATCHN    65536
#define BM        64
#define KC        32                  // k-elems per chunk
#define NITER     (IND / KC)          // 32
#define NTHR      256
#define NS        3

#define PITCHB    80                  // bytes per fp16 smem row (20r mod 32 distinct)
#define PITCHH    40
#define PANEL_H   (ODIM * PITCHH)     // 5120 halves per W k-panel (10240 B)
#define W_BYTES   10240

#define SM_MBAR     0                 // 3 mbarriers
#define SM_COEF     256
#define SM_SLOT     2048
#define SLOT_BYTES  30720             // x 5120 + y 5120 + W0 10240 + W1 10240
#define TO_X        0
#define TO_Y        5120
#define TO_W0       10240
#define TO_W1       20480
#define W_TX        (2 * W_BYTES)
#define SMEM_TOTAL  (SM_SLOT + NS * SLOT_BYTES)     // 94208 -> 2 CTAs/SM
#define EXP         132

typedef uint32_t U32;

__device__ __align__(1024) __half g_W0h[NITER * PANEL_H];
__device__ __align__(1024) __half g_W1h[NITER * PANEL_H];

// ---------------- PTX helpers ----------------

static __device__ __forceinline__ U32 s2u(const void* p) {
    U32 a;
    asm("{ .reg .u64 t; cvta.to.shared.u64 t, %1; cvt.u32.u64 %0, t; }" : "=r"(a) : "l"(p));
    return a;
}

static __device__ __forceinline__ void bulk_g2s(U32 dst, const void* src, U32 bytes, U32 mbar) {
    asm volatile("cp.async.bulk.shared::cluster.global.mbarrier::complete_tx::bytes "
                 "[%0], [%1], %2, [%3];"
                 :: "r"(dst), "l"(src), "r"(bytes), "r"(mbar) : "memory");
}

static __device__ __forceinline__ void mbar_init(U32 a, U32 cnt) {
    asm volatile("mbarrier.init.shared.b64 [%0], %1;" :: "r"(a), "r"(cnt) : "memory");
}
static __device__ __forceinline__ void mbar_expect(U32 a, U32 tx) {
    asm volatile("mbarrier.arrive.expect_tx.shared.b64 _, [%0], %1;" :: "r"(a), "r"(tx) : "memory");
}

#define MBAR_WAIT(addr, par) do {                                              \
    asm volatile("{\n\t.reg .pred P1;\n\t"                                     \
        "LAB_W_%=:\n\t"                                                        \
        "mbarrier.try_wait.parity.acquire.cta.shared::cta.b64 P1, [%0], %1, 0x989680;\n\t" \
        "@P1 bra.uni LAB_D_%=;\n\t"                                            \
        "bra.uni LAB_W_%=;\n\t"                                                \
        "LAB_D_%=:\n\t}"                                                       \
        :: "r"(addr), "r"(par) : "memory");                                    \
} while (0)

static __device__ __forceinline__ void ldsm4(U32& r0, U32& r1, U32& r2, U32& r3, U32 addr) {
    asm volatile("ldmatrix.sync.aligned.m8n8.x4.shared.b16 {%0,%1,%2,%3}, [%4];"
                 : "=r"(r0), "=r"(r1), "=r"(r2), "=r"(r3) : "r"(addr));
}

static __device__ __forceinline__ void mma16(float* c, U32 a0, U32 a1, U32 a2, U32 a3,
                                             U32 b0, U32 b1) {
    asm volatile("mma.sync.aligned.m16n8k16.row.col.f32.f16.f16.f32 "
                 "{%0,%1,%2,%3}, {%4,%5,%6,%7}, {%8,%9}, {%0,%1,%2,%3};"
                 : "+f"(c[0]), "+f"(c[1]), "+f"(c[2]), "+f"(c[3])
                 : "r"(a0), "r"(a1), "r"(a2), "r"(a3), "r"(b0), "r"(b1));
}

static __device__ __forceinline__ U32 cvt2h(float lo, float hi) {
    U32 r;
    asm("cvt.rn.f16x2.f32 %0, %1, %2;" : "=r"(r) : "f"(hi), "f"(lo));
    return r;
}

// ---------------- weight normalization + fp16 k-panel packing ----------------
__global__ void normalize_kernel(const float* __restrict__ w) {
    int row  = blockIdx.x & (ODIM - 1);
    int half = blockIdx.x >> 7;
    const float* src = w + (size_t)row * (2 * IND) + (size_t)half * IND;
    __half* dst = half ? g_W1h : g_W0h;
    int t = threadIdx.x;  // 256 threads
    float v[4], s = 0.f, s2 = 0.f;
#pragma unroll
    for (int i = 0; i < 4; ++i) { v[i] = src[t + 256 * i]; s += v[i]; s2 += v[i] * v[i]; }
#pragma unroll
    for (int o = 16; o; o >>= 1) {
        s  += __shfl_xor_sync(~0u, s,  o);
        s2 += __shfl_xor_sync(~0u, s2, o);
    }
    __shared__ float sh[18];
    if ((t & 31) == 0) { sh[t >> 5] = s; sh[8 + (t >> 5)] = s2; }
    __syncthreads();
    if (t == 0) {
        float S = 0.f, S2 = 0.f;
#pragma unroll
        for (int i = 0; i < 8; ++i) { S += sh[i]; S2 += sh[8 + i]; }
        float mu = S * (1.f / IND);
        float ss = S2 - (float)IND * mu * mu;
        sh[16] = mu; sh[17] = rsqrtf(ss);
    }
    __syncthreads();
    float mu = sh[16], inv = sh[17];
#pragma unroll
    for (int i = 0; i < 4; ++i) {
        int k  = t + 256 * i;
        int kc = k >> 5, col = k & 31;
        dst[(size_t)kc * PANEL_H + row * PITCHH + col] = __float2half((v[i] - mu) * inv);
    }
    {
        int kc = t >> 3, pc = 32 + (t & 7);
        dst[(size_t)kc * PANEL_H + row * PITCHH + pc] = __float2half(0.f);
    }
}

// ------- main fused GEMM (fp16, KC=32, NS=3, producers at iteration top) ----------
// 8 warps: warps 0-3: out0 = x*W0^T, warps 4-7: out1 = y*W1^T. Warp tile 32x64.
// iter i: [stash chunk i+2 -> slot (i+2)%3; TMA W i+2; LDG i+3] -> compute chunk i
//         -> cvt LDG regs -> wait mbar slot (i+1)%3 -> ONE syncthreads.

__global__ void __launch_bounds__(NTHR, 2)
gemm_kernel(const float* __restrict__ x, const float* __restrict__ y,
            const float* __restrict__ fc_bias, const float* __restrict__ a0,
            const float* __restrict__ a1, float* __restrict__ out) {
    extern __shared__ char smem[];
    const U32 sb = s2u(smem);
    const int tid = threadIdx.x;
    const int wid = tid >> 5, lid = tid & 31;
    const int m0 = blockIdx.x * BM;

    if (tid == 0) {
#pragma unroll
        for (int s = 0; s < NS; ++s) mbar_init(sb + SM_MBAR + s * 8, 1);
    }
    if (tid < 128) {
        float* sc = (float*)(smem + SM_COEF);
        sc[tid] = a0[tid]; sc[128 + tid] = a1[tid]; sc[256 + tid] = fc_bias[tid];
    }
    __syncthreads();

    // per-thread x/y lanes: rows r0, r0+32; 16B chunk ch of each 128B row
    const int ch = tid & 7;
    const int r0 = tid >> 3;
    const float* px = x + (size_t)(m0 + r0) * IND + ch * 4;
    const float* py = y + (size_t)(m0 + r0) * IND + ch * 4;
    const size_t rstep = (size_t)32 * IND;
    const U32 d0 = (U32)(r0 * PITCHB + ch * 8);
    const U32 d1 = (U32)((r0 + 32) * PITCHB + ch * 8);

    // stash 8 converted half2 regs into slot st
    auto stash = [&](U32 st, const U32* h) {
        asm volatile("st.shared.v2.b32 [%0], {%1,%2};" :: "r"(st + TO_X + d0), "r"(h[0]), "r"(h[1]));
        asm volatile("st.shared.v2.b32 [%0], {%1,%2};" :: "r"(st + TO_X + d1), "r"(h[2]), "r"(h[3]));
        asm volatile("st.shared.v2.b32 [%0], {%1,%2};" :: "r"(st + TO_Y + d0), "r"(h[4]), "r"(h[5]));
        asm volatile("st.shared.v2.b32 [%0], {%1,%2};" :: "r"(st + TO_Y + d1), "r"(h[6]), "r"(h[7]));
    };

    // prologue: chunks 0,1 direct to slots 0,1; W TMA chunks 0,1; LDG chunk 2
    if (tid == 0) {
#pragma unroll
        for (int s = 0; s < 2; ++s) {
            const U32 mb = sb + SM_MBAR + s * 8;
            const U32 st = sb + SM_SLOT + (U32)(s * SLOT_BYTES);
            mbar_expect(mb, W_TX);
            bulk_g2s(st + TO_W0, g_W0h + (size_t)s * PANEL_H, W_BYTES, mb);
            bulk_g2s(st + TO_W1, g_W1h + (size_t)s * PANEL_H, W_BYTES, mb);
        }
    }
#pragma unroll
    for (int s = 0; s < 2; ++s) {
        const U32 st = sb + SM_SLOT + (U32)(s * SLOT_BYTES);
        U32 h[8];
        float4 v;
        v = *(const float4*)(px + s * KC);         h[0] = cvt2h(v.x, v.y); h[1] = cvt2h(v.z, v.w);
        v = *(const float4*)(px + s * KC + rstep); h[2] = cvt2h(v.x, v.y); h[3] = cvt2h(v.z, v.w);
        v = *(const float4*)(py + s * KC);         h[4] = cvt2h(v.x, v.y); h[5] = cvt2h(v.z, v.w);
        v = *(const float4*)(py + s * KC + rstep); h[6] = cvt2h(v.x, v.y); h[7] = cvt2h(v.z, v.w);
        stash(st, h);
    }
    // LDG chunk 2 into regs, convert
    U32 hbuf[8];
    {
        float4 v;
        v = *(const float4*)(px + 2 * KC);         hbuf[0] = cvt2h(v.x, v.y); hbuf[1] = cvt2h(v.z, v.w);
        v = *(const float4*)(px + 2 * KC + rstep); hbuf[2] = cvt2h(v.x, v.y); hbuf[3] = cvt2h(v.z, v.w);
        v = *(const float4*)(py + 2 * KC);         hbuf[4] = cvt2h(v.x, v.y); hbuf[5] = cvt2h(v.z, v.w);
        v = *(const float4*)(py + 2 * KC + rstep); hbuf[6] = cvt2h(v.x, v.y); hbuf[7] = cvt2h(v.z, v.w);
    }
    const float* plx = px + 3 * KC;
    const float* ply = py + 3 * KC;

    MBAR_WAIT(sb + SM_MBAR + 0, 0u);
    __syncthreads();                     // slots 0,1 stashed; slot 0 W ready

    // warp role
    const int g1 = wid >> 2;
    const int wl = wid & 3;
    const int mw = wl & 1;
    const int nw = wl >> 1;

    const int sel  = lid >> 3;
    const int lrow = lid & 7;
    const int aRowL = (sel & 1) * 8 + lrow;
    const U32 aKb   = (U32)((sel >> 1) * 16);
    const int bRowL = sel * 8 + lrow;

    U32 aOff[2];
#pragma unroll
    for (int mt = 0; mt < 2; ++mt)
        aOff[mt] = (U32)((mw * 32 + mt * 16 + aRowL) * PITCHB) + aKb;
    U32 bOff[2];
#pragma unroll
    for (int g = 0; g < 2; ++g)
        bOff[g] = (U32)((nw * 64 + g * 32 + bRowL) * PITCHB);

    float acc[2][8][4];
#pragma unroll
    for (int mt = 0; mt < 2; ++mt)
#pragma unroll
        for (int nt = 0; nt < 8; ++nt)
#pragma unroll
            for (int q = 0; q < 4; ++q) acc[mt][nt][q] = 0.f;

    const U32 toA = g1 ? TO_Y : TO_X;
    const U32 toB = g1 ? TO_W1 : TO_W0;

    int ph0 = 1, ph1 = 0, ph2 = 0;       // slot0 phase0 consumed at entry
    for (int i = 0; i < NITER; ++i) {
        const int cs = i % NS;

        // -------- producer work at top: slot (i+2)%NS is free since last boundary
        if (i + 2 < NITER) {
            const int fs = (i + 2) % NS;
            const U32 stf = sb + SM_SLOT + (U32)(fs * SLOT_BYTES);
            stash(stf, hbuf);
            if (tid == 0) {
                const U32 mb = sb + SM_MBAR + fs * 8;
                mbar_expect(mb, W_TX);
                bulk_g2s(stf + TO_W0, g_W0h + (size_t)(i + 2) * PANEL_H, W_BYTES, mb);
                bulk_g2s(stf + TO_W1, g_W1h + (size_t)(i + 2) * PANEL_H, W_BYTES, mb);
            }
        }
        // issue LDG for chunk i+3 (in flight across compute)
        float4 xv0, xv1, yv0, yv1;
        const bool ldg = (i + 3 < NITER);
        if (ldg) {
            xv0 = *(const float4*)(plx);
            xv1 = *(const float4*)(plx + rstep);
            yv0 = *(const float4*)(ply);
            yv1 = *(const float4*)(ply + rstep);
            plx += KC; ply += KC;
        }

        // -------- compute chunk i
        const U32 st = sb + SM_SLOT + (U32)(cs * SLOT_BYTES);
        const U32 abase = st + toA;
        const U32 bbase = st + toB;
#pragma unroll
        for (int ks = 0; ks < 2; ++ks) {
            const U32 kb = (U32)(ks * 32);
            U32 a[2][4];
#pragma unroll
            for (int mt = 0; mt < 2; ++mt)
                ldsm4(a[mt][0], a[mt][1], a[mt][2], a[mt][3], abase + aOff[mt] + kb);
#pragma unroll
            for (int g = 0; g < 2; ++g) {
                U32 b0[4], b1[4];
                ldsm4(b0[0], b0[1], b0[2], b0[3], bbase + bOff[g] + kb);
                ldsm4(b1[0], b1[1], b1[2], b1[3], bbase + bOff[g] + kb + 16u);
#pragma unroll
                for (int mt = 0; mt < 2; ++mt)
#pragma unroll
                    for (int j = 0; j < 4; ++j)
                        mma16(acc[mt][4 * g + j], a[mt][0], a[mt][1], a[mt][2], a[mt][3],
                              b0[j], b1[j]);
            }
        }

        // convert in-flight LDGs (data has arrived under compute)
        if (ldg) {
            hbuf[0] = cvt2h(xv0.x, xv0.y); hbuf[1] = cvt2h(xv0.z, xv0.w);
            hbuf[2] = cvt2h(xv1.x, xv1.y); hbuf[3] = cvt2h(xv1.z, xv1.w);
            hbuf[4] = cvt2h(yv0.x, yv0.y); hbuf[5] = cvt2h(yv0.z, yv0.w);
            hbuf[6] = cvt2h(yv1.x, yv1.y); hbuf[7] = cvt2h(yv1.z, yv1.w);
        }

        // -------- boundary: make chunk i+1 ready; nothing after the barrier
        if (i + 1 < NITER) {
            const int ws = (i + 1) % NS;
            int ph = (ws == 0) ? ph0 : (ws == 1) ? ph1 : ph2;
            MBAR_WAIT(sb + SM_MBAR + ws * 8, (U32)ph);
            if (ws == 0) ph0 ^= 1; else if (ws == 1) ph1 ^= 1; else ph2 ^= 1;
            __syncthreads();
        }
    }
    __syncthreads();

    // ---------- epilogue ----------
    float* exch = (float*)(smem + SM_SLOT);
    const float* sa0 = (const float*)(smem + SM_COEF);
    const float* sa1 = sa0 + 128;
    const float* sbs = sa0 + 256;

    const int rowb = mw * 32 + (lid >> 2);
    const int colb = nw * 64 + 2 * (lid & 3);

    if (!g1) {
#pragma unroll
        for (int mt = 0; mt < 2; ++mt) {
            const int rl = rowb + mt * 16;
#pragma unroll
            for (int nt = 0; nt < 8; ++nt) {
                const int c = colb + nt * 8;
                float2 v0 = make_float2(acc[mt][nt][0], acc[mt][nt][1]);
                float2 v1 = make_float2(acc[mt][nt][2], acc[mt][nt][3]);
                *(float2*)(out + (size_t)(m0 + rl)     * ODIM + c) = v0;
                *(float2*)(out + (size_t)(m0 + rl + 8) * ODIM + c) = v1;
                *(float2*)(exch + rl * EXP + c)       = v0;
                *(float2*)(exch + (rl + 8) * EXP + c) = v1;
            }
        }
    } else {
        float* o1 = out + (size_t)BATCHN * ODIM;
#pragma unroll
        for (int mt = 0; mt < 2; ++mt) {
            const int rl = rowb + mt * 16;
#pragma unroll
            for (int nt = 0; nt < 8; ++nt) {
                const int c = colb + nt * 8;
                *(float2*)(o1 + (size_t)(m0 + rl)     * ODIM + c) =
                    make_float2(acc[mt][nt][0], acc[mt][nt][1]);
                *(float2*)(o1 + (size_t)(m0 + rl + 8) * ODIM + c) =
                    make_float2(acc[mt][nt][2], acc[mt][nt][3]);
            }
        }
    }
    __syncthreads();

    if (g1) {
        float* o2 = out + 2 * (size_t)BATCHN * ODIM;
#pragma unroll
        for (int mt = 0; mt < 2; ++mt) {
            const int rl = rowb + mt * 16;
#pragma unroll
            for (int nt = 0; nt < 8; ++nt) {
                const int c = colb + nt * 8;
                float2 p0 = *(const float2*)(exch + rl * EXP + c);
                float2 p1 = *(const float2*)(exch + (rl + 8) * EXP + c);
                const float A0x = sa0[c], A0y = sa0[c + 1];
                const float A1x = sa1[c], A1y = sa1[c + 1];
                const float Bx  = sbs[c], By  = sbs[c + 1];
                float2 r0, r1;
                r0.x = p0.x * A0x + acc[mt][nt][0] * A1x + Bx;
                r0.y = p0.y * A0y + acc[mt][nt][1] * A1y + By;
                r1.x = p1.x * A0x + acc[mt][nt][2] * A1x + Bx;
                r1.y = p1.y * A0y + acc[mt][nt][3] * A1y + By;
                *(float2*)(o2 + (size_t)(m0 + rl)     * ODIM + c) = r0;
                *(float2*)(o2 + (size_t)(m0 + rl + 8) * ODIM + c) = r1;
            }
        }
    }
}

// ---------------- launch ----------------

extern "C" void kernel_launch(void* const* d_in, const int* in_sizes, int n_in,
                              void* d_out, int out_size) {
    const float* x  = (const float*)d_in[0];
    const float* y  = (const float*)d_in[1];
    const float* fw = (const float*)d_in[2];
    const float* fb = (const float*)d_in[3];
    const float* a0 = (const float*)d_in[4];
    const float* a1 = (const float*)d_in[5];
    float* out = (float*)d_out;

    normalize_kernel<<<2 * ODIM, 256>>>(fw);

    cudaFuncSetAttribute(gemm_kernel, cudaFuncAttributeMaxDynamicSharedMemorySize, SMEM_TOTAL);
    gemm_kernel<<<BATCHN / BM, NTHR, SMEM_TOTAL>>>(x, y, fb, a0, a1, out);
}

// round 16
// speedup vs baseline: 1.4013x; 1.0111x over previous
#include <cuda_runtime.h>
#include <cuda_fp16.h>
#include <cstdint>

#define IND       1024
#define ODIM      128
#define BATCHN    65536
#define BM        64
#define KC        32                  // k-elems per chunk
#define NITER     (IND / KC)          // 32
#define NTHR      256
#define NS        3

#define PITCHB    80                  // bytes per fp16 smem row (20r mod 32 distinct)
#define PITCHH    40
#define PANEL_H   (ODIM * PITCHH)     // 5120 halves per W k-panel (10240 B)
#define W_BYTES   10240

#define SM_MBAR     0                 // 3 mbarriers
#define SM_COEF     256
#define SM_SLOT     2048
#define SLOT_BYTES  30720             // x 5120 + y 5120 + W0 10240 + W1 10240
#define TO_X        0
#define TO_Y        5120
#define TO_W0       10240
#define TO_W1       20480
#define W_TX        (2 * W_BYTES)
#define SMEM_TOTAL  (SM_SLOT + NS * SLOT_BYTES)     // 94208 -> 2 CTAs/SM
#define EXP         132

typedef uint32_t U32;

__device__ __align__(1024) __half g_W0h[NITER * PANEL_H];
__device__ __align__(1024) __half g_W1h[NITER * PANEL_H];

// ---------------- PTX helpers ----------------

static __device__ __forceinline__ U32 s2u(const void* p) {
    U32 a;
    asm("{ .reg .u64 t; cvta.to.shared.u64 t, %1; cvt.u32.u64 %0, t; }" : "=r"(a) : "l"(p));
    return a;
}

static __device__ __forceinline__ void bulk_g2s(U32 dst, const void* src, U32 bytes, U32 mbar) {
    asm volatile("cp.async.bulk.shared::cluster.global.mbarrier::complete_tx::bytes "
                 "[%0], [%1], %2, [%3];"
                 :: "r"(dst), "l"(src), "r"(bytes), "r"(mbar) : "memory");
}

static __device__ __forceinline__ void mbar_init(U32 a, U32 cnt) {
    asm volatile("mbarrier.init.shared.b64 [%0], %1;" :: "r"(a), "r"(cnt) : "memory");
}
static __device__ __forceinline__ void mbar_expect(U32 a, U32 tx) {
    asm volatile("mbarrier.arrive.expect_tx.shared.b64 _, [%0], %1;" :: "r"(a), "r"(tx) : "memory");
}

#define MBAR_WAIT(addr, par) do {                                              \
    asm volatile("{\n\t.reg .pred P1;\n\t"                                     \
        "LAB_W_%=:\n\t"                                                        \
        "mbarrier.try_wait.parity.acquire.cta.shared::cta.b64 P1, [%0], %1, 0x989680;\n\t" \
        "@P1 bra.uni LAB_D_%=;\n\t"                                            \
        "bra.uni LAB_W_%=;\n\t"                                                \
        "LAB_D_%=:\n\t}"                                                       \
        :: "r"(addr), "r"(par) : "memory");                                    \
} while (0)

static __device__ __forceinline__ void ldsm4(U32& r0, U32& r1, U32& r2, U32& r3, U32 addr) {
    asm volatile("ldmatrix.sync.aligned.m8n8.x4.shared.b16 {%0,%1,%2,%3}, [%4];"
                 : "=r"(r0), "=r"(r1), "=r"(r2), "=r"(r3) : "r"(addr));
}

static __device__ __forceinline__ void mma16(float* c, U32 a0, U32 a1, U32 a2, U32 a3,
                                             U32 b0, U32 b1) {
    asm volatile("mma.sync.aligned.m16n8k16.row.col.f32.f16.f16.f32 "
                 "{%0,%1,%2,%3}, {%4,%5,%6,%7}, {%8,%9}, {%0,%1,%2,%3};"
                 : "+f"(c[0]), "+f"(c[1]), "+f"(c[2]), "+f"(c[3])
                 : "r"(a0), "r"(a1), "r"(a2), "r"(a3), "r"(b0), "r"(b1));
}

static __device__ __forceinline__ U32 cvt2h(float lo, float hi) {
    U32 r;
    asm("cvt.rn.f16x2.f32 %0, %1, %2;" : "=r"(r) : "f"(hi), "f"(lo));
    return r;
}

// ---------------- weight normalization + fp16 k-panel packing ----------------
__global__ void normalize_kernel(const float* __restrict__ w) {
    int row  = blockIdx.x & (ODIM - 1);
    int half = blockIdx.x >> 7;
    const float* src = w + (size_t)row * (2 * IND) + (size_t)half * IND;
    __half* dst = half ? g_W1h : g_W0h;
    int t = threadIdx.x;  // 256 threads
    float v[4], s = 0.f, s2 = 0.f;
#pragma unroll
    for (int i = 0; i < 4; ++i) { v[i] = src[t + 256 * i]; s += v[i]; s2 += v[i] * v[i]; }
#pragma unroll
    for (int o = 16; o; o >>= 1) {
        s  += __shfl_xor_sync(~0u, s,  o);
        s2 += __shfl_xor_sync(~0u, s2, o);
    }
    __shared__ float sh[18];
    if ((t & 31) == 0) { sh[t >> 5] = s; sh[8 + (t >> 5)] = s2; }
    __syncthreads();
    if (t == 0) {
        float S = 0.f, S2 = 0.f;
#pragma unroll
        for (int i = 0; i < 8; ++i) { S += sh[i]; S2 += sh[8 + i]; }
        float mu = S * (1.f / IND);
        float ss = S2 - (float)IND * mu * mu;
        sh[16] = mu; sh[17] = rsqrtf(ss);
    }
    __syncthreads();
    float mu = sh[16], inv = sh[17];
#pragma unroll
    for (int i = 0; i < 4; ++i) {
        int k  = t + 256 * i;
        int kc = k >> 5, col = k & 31;
        dst[(size_t)kc * PANEL_H + row * PITCHH + col] = __float2half((v[i] - mu) * inv);
    }
    {
        int kc = t >> 3, pc = 32 + (t & 7);
        dst[(size_t)kc * PANEL_H + row * PITCHH + pc] = __float2half(0.f);
    }
}

// ------- main fused GEMM (fp16, KC=32, NS=3, producers in the shadow) -------------
// 8 warps: warps 0-3: out0 = x*W0^T, warps 4-7: out1 = y*W1^T. Warp tile 32x64.
// iter i: LDG i+3 -> compute slot i%3 -> stash chunk i+2 -> slot (i+2)%3, cvt LDGs
//         -> wait mbar slot (i+1)%3 (armed 2 iters ago) -> ONE sync -> TMA W i+3.

__global__ void __launch_bounds__(NTHR, 2)
gemm_kernel(const float* __restrict__ x, const float* __restrict__ y,
            const float* __restrict__ fc_bias, const float* __restrict__ a0,
            const float* __restrict__ a1, float* __restrict__ out) {
    extern __shared__ char smem[];
    const U32 sb = s2u(smem);
    const int tid = threadIdx.x;
    const int wid = tid >> 5, lid = tid & 31;
    const int m0 = blockIdx.x * BM;

    if (tid == 0) {
#pragma unroll
        for (int s = 0; s < NS; ++s) mbar_init(sb + SM_MBAR + s * 8, 1);
    }
    if (tid < 128) {
        float* sc = (float*)(smem + SM_COEF);
        sc[tid] = a0[tid]; sc[128 + tid] = a1[tid]; sc[256 + tid] = fc_bias[tid];
    }
    __syncthreads();

    // per-thread x/y lanes: rows r0, r0+32; 16B chunk ch of each 128B row
    const int ch = tid & 7;
    const int r0 = tid >> 3;
    const float* px = x + (size_t)(m0 + r0) * IND + ch * 4;
    const float* py = y + (size_t)(m0 + r0) * IND + ch * 4;
    const size_t rstep = (size_t)32 * IND;
    const U32 d0 = (U32)(r0 * PITCHB + ch * 8);
    const U32 d1 = (U32)((r0 + 32) * PITCHB + ch * 8);

    auto stash = [&](U32 st, const U32* h) {
        asm volatile("st.shared.v2.b32 [%0], {%1,%2};" :: "r"(st + TO_X + d0), "r"(h[0]), "r"(h[1]));
        asm volatile("st.shared.v2.b32 [%0], {%1,%2};" :: "r"(st + TO_X + d1), "r"(h[2]), "r"(h[3]));
        asm volatile("st.shared.v2.b32 [%0], {%1,%2};" :: "r"(st + TO_Y + d0), "r"(h[4]), "r"(h[5]));
        asm volatile("st.shared.v2.b32 [%0], {%1,%2};" :: "r"(st + TO_Y + d1), "r"(h[6]), "r"(h[7]));
    };

    // prologue: W TMA for chunks 0,1,2 (all 3 slots free); x/y chunks 0,1 direct;
    // hbuf = cvt(LDG chunk 2)
    if (tid == 0) {
#pragma unroll
        for (int s = 0; s < NS; ++s) {
            const U32 mb = sb + SM_MBAR + s * 8;
            const U32 st = sb + SM_SLOT + (U32)(s * SLOT_BYTES);
            mbar_expect(mb, W_TX);
            bulk_g2s(st + TO_W0, g_W0h + (size_t)s * PANEL_H, W_BYTES, mb);
            bulk_g2s(st + TO_W1, g_W1h + (size_t)s * PANEL_H, W_BYTES, mb);
        }
    }
#pragma unroll
    for (int s = 0; s < 2; ++s) {
        const U32 st = sb + SM_SLOT + (U32)(s * SLOT_BYTES);
        U32 h[8];
        float4 v;
        v = *(const float4*)(px + s * KC);         h[0] = cvt2h(v.x, v.y); h[1] = cvt2h(v.z, v.w);
        v = *(const float4*)(px + s * KC + rstep); h[2] = cvt2h(v.x, v.y); h[3] = cvt2h(v.z, v.w);
        v = *(const float4*)(py + s * KC);         h[4] = cvt2h(v.x, v.y); h[5] = cvt2h(v.z, v.w);
        v = *(const float4*)(py + s * KC + rstep); h[6] = cvt2h(v.x, v.y); h[7] = cvt2h(v.z, v.w);
        stash(st, h);
    }
    U32 hbuf[8];
    {
        float4 v;
        v = *(const float4*)(px + 2 * KC);         hbuf[0] = cvt2h(v.x, v.y); hbuf[1] = cvt2h(v.z, v.w);
        v = *(const float4*)(px + 2 * KC + rstep); hbuf[2] = cvt2h(v.x, v.y); hbuf[3] = cvt2h(v.z, v.w);
        v = *(const float4*)(py + 2 * KC);         hbuf[4] = cvt2h(v.x, v.y); hbuf[5] = cvt2h(v.z, v.w);
        v = *(const float4*)(py + 2 * KC + rstep); hbuf[6] = cvt2h(v.x, v.y); hbuf[7] = cvt2h(v.z, v.w);
    }
    const float* plx = px + 3 * KC;
    const float* ply = py + 3 * KC;

    MBAR_WAIT(sb + SM_MBAR + 0, 0u);
    __syncthreads();                     // slot 0 fully ready

    // warp role
    const int g1 = wid >> 2;
    const int wl = wid & 3;
    const int mw = wl & 1;
    const int nw = wl >> 1;

    const int sel  = lid >> 3;
    const int lrow = lid & 7;
    const int aRowL = (sel & 1) * 8 + lrow;
    const U32 aKb   = (U32)((sel >> 1) * 16);
    const int bRowL = sel * 8 + lrow;

    U32 aOff[2];
#pragma unroll
    for (int mt = 0; mt < 2; ++mt)
        aOff[mt] = (U32)((mw * 32 + mt * 16 + aRowL) * PITCHB) + aKb;
    U32 bOff[2];
#pragma unroll
    for (int g = 0; g < 2; ++g)
        bOff[g] = (U32)((nw * 64 + g * 32 + bRowL) * PITCHB);

    float acc[2][8][4];
#pragma unroll
    for (int mt = 0; mt < 2; ++mt)
#pragma unroll
        for (int nt = 0; nt < 8; ++nt)
#pragma unroll
            for (int q = 0; q < 4; ++q) acc[mt][nt][q] = 0.f;

    const U32 toA = g1 ? TO_Y : TO_X;
    const U32 toB = g1 ? TO_W1 : TO_W0;

    int ph0 = 1, ph1 = 0, ph2 = 0;       // slot0 phase0 consumed at entry
    for (int i = 0; i < NITER; ++i) {
        const int cs = i % NS;

        // LDG chunk i+3 (in flight under compute)
        float4 xv0, xv1, yv0, yv1;
        const bool ldg = (i + 3 < NITER);
        if (ldg) {
            xv0 = *(const float4*)(plx);
            xv1 = *(const float4*)(plx + rstep);
            yv0 = *(const float4*)(ply);
            yv1 = *(const float4*)(ply + rstep);
            plx += KC; ply += KC;
        }

        // compute chunk i
        const U32 st = sb + SM_SLOT + (U32)(cs * SLOT_BYTES);
        const U32 abase = st + toA;
        const U32 bbase = st + toB;
#pragma unroll
        for (int ks = 0; ks < 2; ++ks) {
            const U32 kb = (U32)(ks * 32);
            U32 a[2][4];
#pragma unroll
            for (int mt = 0; mt < 2; ++mt)
                ldsm4(a[mt][0], a[mt][1], a[mt][2], a[mt][3], abase + aOff[mt] + kb);
#pragma unroll
            for (int g = 0; g < 2; ++g) {
                U32 b0[4], b1[4];
                ldsm4(b0[0], b0[1], b0[2], b0[3], bbase + bOff[g] + kb);
                ldsm4(b1[0], b1[1], b1[2], b1[3], bbase + bOff[g] + kb + 16u);
#pragma unroll
                for (int mt = 0; mt < 2; ++mt)
#pragma unroll
                    for (int j = 0; j < 4; ++j)
                        mma16(acc[mt][4 * g + j], a[mt][0], a[mt][1], a[mt][2], a[mt][3],
                              b0[j], b1[j]);
            }
        }

        // shadow: stash chunk i+2 into slot (i+2)%3 (free since barrier end of i-1)
        if (i + 2 < NITER) {
            const U32 stf = sb + SM_SLOT + (U32)(((i + 2) % NS) * SLOT_BYTES);
            stash(stf, hbuf);
        }
        // convert in-flight LDGs (chunk i+3)
        if (ldg) {
            hbuf[0] = cvt2h(xv0.x, xv0.y); hbuf[1] = cvt2h(xv0.z, xv0.w);
            hbuf[2] = cvt2h(xv1.x, xv1.y); hbuf[3] = cvt2h(xv1.z, xv1.w);
            hbuf[4] = cvt2h(yv0.x, yv0.y); hbuf[5] = cvt2h(yv0.z, yv0.w);
            hbuf[6] = cvt2h(yv1.x, yv1.y); hbuf[7] = cvt2h(yv1.z, yv1.w);
        }

        // boundary: chunk i+1's W armed 2 iterations ago -> fast path
        if (i + 1 < NITER) {
            const int ws = (i + 1) % NS;
            int ph = (ws == 0) ? ph0 : (ws == 1) ? ph1 : ph2;
            MBAR_WAIT(sb + SM_MBAR + ws * 8, (U32)ph);
            if (ws == 0) ph0 ^= 1; else if (ws == 1) ph1 ^= 1; else ph2 ^= 1;
            __syncthreads();
            // slot cs now free: issue W TMA for chunk i+3 (2+ iterations of lead)
            if (i + 3 < NITER && tid == 0) {
                const U32 mb = sb + SM_MBAR + cs * 8;
                mbar_expect(mb, W_TX);
                bulk_g2s(st + TO_W0, g_W0h + (size_t)(i + 3) * PANEL_H, W_BYTES, mb);
                bulk_g2s(st + TO_W1, g_W1h + (size_t)(i + 3) * PANEL_H, W_BYTES, mb);
            }
        }
    }
    __syncthreads();

    // ---------- epilogue ----------
    float* exch = (float*)(smem + SM_SLOT);
    const float* sa0 = (const float*)(smem + SM_COEF);
    const float* sa1 = sa0 + 128;
    const float* sbs = sa0 + 256;

    const int rowb = mw * 32 + (lid >> 2);
    const int colb = nw * 64 + 2 * (lid & 3);

    if (!g1) {
#pragma unroll
        for (int mt = 0; mt < 2; ++mt) {
            const int rl = rowb + mt * 16;
#pragma unroll
            for (int nt = 0; nt < 8; ++nt) {
                const int c = colb + nt * 8;
                float2 v0 = make_float2(acc[mt][nt][0], acc[mt][nt][1]);
                float2 v1 = make_float2(acc[mt][nt][2], acc[mt][nt][3]);
                *(float2*)(out + (size_t)(m0 + rl)     * ODIM + c) = v0;
                *(float2*)(out + (size_t)(m0 + rl + 8) * ODIM + c) = v1;
                *(float2*)(exch + rl * EXP + c)       = v0;
                *(float2*)(exch + (rl + 8) * EXP + c) = v1;
            }
        }
    } else {
        float* o1 = out + (size_t)BATCHN * ODIM;
#pragma unroll
        for (int mt = 0; mt < 2; ++mt) {
            const int rl = rowb + mt * 16;
#pragma unroll
            for (int nt = 0; nt < 8; ++nt) {
                const int c = colb + nt * 8;
                *(float2*)(o1 + (size_t)(m0 + rl)     * ODIM + c) =
                    make_float2(acc[mt][nt][0], acc[mt][nt][1]);
                *(float2*)(o1 + (size_t)(m0 + rl + 8) * ODIM + c) =
                    make_float2(acc[mt][nt][2], acc[mt][nt][3]);
            }
        }
    }
    __syncthreads();

    if (g1) {
        float* o2 = out + 2 * (size_t)BATCHN * ODIM;
#pragma unroll
        for (int mt = 0; mt < 2; ++mt) {
            const int rl = rowb + mt * 16;
#pragma unroll
            for (int nt = 0; nt < 8; ++nt) {
                const int c = colb + nt * 8;
                float2 p0 = *(const float2*)(exch + rl * EXP + c);
                float2 p1 = *(const float2*)(exch + (rl + 8) * EXP + c);
                const float A0x = sa0[c], A0y = sa0[c + 1];
                const float A1x = sa1[c], A1y = sa1[c + 1];
                const float Bx  = sbs[c], By  = sbs[c + 1];
                float2 r0, r1;
                r0.x = p0.x * A0x + acc[mt][nt][0] * A1x + Bx;
                r0.y = p0.y * A0y + acc[mt][nt][1] * A1y + By;
                r1.x = p1.x * A0x + acc[mt][nt][2] * A1x + Bx;
                r1.y = p1.y * A0y + acc[mt][nt][3] * A1y + By;
                *(float2*)(o2 + (size_t)(m0 + rl)     * ODIM + c) = r0;
                *(float2*)(o2 + (size_t)(m0 + rl + 8) * ODIM + c) = r1;
            }
        }
    }
}

// ---------------- launch ----------------

extern "C" void kernel_launch(void* const* d_in, const int* in_sizes, int n_in,
                              void* d_out, int out_size) {
    const float* x  = (const float*)d_in[0];
    const float* y  = (const float*)d_in[1];
    const float* fw = (const float*)d_in[2];
    const float* fb = (const float*)d_in[3];
    const float* a0 = (const float*)d_in[4];
    const float* a1 = (const float*)d_in[5];
    float* out = (float*)d_out;

    normalize_kernel<<<2 * ODIM, 256>>>(fw);

    cudaFuncSetAttribute(gemm_kernel, cudaFuncAttributeMaxDynamicSharedMemorySize, SMEM_TOTAL);
    gemm_kernel<<<BATCHN / BM, NTHR, SMEM_TOTAL>>>(x, y, fb, a0, a1, out);
}

// round 17
// speedup vs baseline: 1.5844x; 1.1306x over previous
#include <cuda_runtime.h>
#include <cuda_fp16.h>
#include <cstdint>

#define IND       1024
#define ODIM      128
#define BATCHN    65536
#define BM        64
#define KC        32                  // k-elems per chunk
#define NITER     (IND / KC)          // 32
#define NTHR      256

#define PITCHB    80                  // bytes per fp16 smem row (20r mod 32 distinct)
#define PITCHH    40                  // halves per row
#define PANEL_H   (ODIM * PITCHH)     // 5120 halves per W k-panel (10240 B)
#define W_BYTES   10240

#define SM_MBAR     0                 // 2 mbarriers
#define SM_COEF     256
#define SM_SLOT     2048              // 2 MMA slots (fp16)
#define SLOT_BYTES  30720             // x 5120 + y 5120 + W0 10240 + W1 10240
#define TO_X        0
#define TO_Y        5120
#define TO_W0       10240
#define TO_W1       20480
#define SM_STG      (SM_SLOT + 2 * SLOT_BYTES)      // fp32 staging, 2 slots
#define STG_BYTES   16384             // x 8KB + y 8KB
#define W_TX        (2 * W_BYTES)
#define SMEM_TOTAL  (SM_STG + 2 * STG_BYTES)        // 96256 -> 2 CTAs/SM
#define EXP         132

typedef uint32_t U32;

// W normalized + fp16 + 80B-pitch k-panels (pad cols zeroed)
__device__ __align__(1024) __half g_W0h[NITER * PANEL_H];
__device__ __align__(1024) __half g_W1h[NITER * PANEL_H];

// ---------------- PTX helpers ----------------

static __device__ __forceinline__ U32 s2u(const void* p) {
    U32 a;
    asm("{ .reg .u64 t; cvta.to.shared.u64 t, %1; cvt.u32.u64 %0, t; }" : "=r"(a) : "l"(p));
    return a;
}

static __device__ __forceinline__ void cp16(U32 dst, const void* src) {
    asm volatile("cp.async.cg.shared.global [%0], [%1], 16;" :: "r"(dst), "l"(src));
}
static __device__ __forceinline__ void cp_commit() {
    asm volatile("cp.async.commit_group;" ::: "memory");
}
template <int N> static __device__ __forceinline__ void cp_wait() {
    asm volatile("cp.async.wait_group %0;" :: "n"(N) : "memory");
}

static __device__ __forceinline__ void bulk_g2s(U32 dst, const void* src, U32 bytes, U32 mbar) {
    asm volatile("cp.async.bulk.shared::cluster.global.mbarrier::complete_tx::bytes "
                 "[%0], [%1], %2, [%3];"
                 :: "r"(dst), "l"(src), "r"(bytes), "r"(mbar) : "memory");
}

static __device__ __forceinline__ void mbar_init(U32 a, U32 cnt) {
    asm volatile("mbarrier.init.shared.b64 [%0], %1;" :: "r"(a), "r"(cnt) : "memory");
}
static __device__ __forceinline__ void mbar_expect(U32 a, U32 tx) {
    asm volatile("mbarrier.arrive.expect_tx.shared.b64 _, [%0], %1;" :: "r"(a), "r"(tx) : "memory");
}

#define MBAR_WAIT(addr, par) do {                                              \
    asm volatile("{\n\t.reg .pred P1;\n\t"                                     \
        "LAB_W_%=:\n\t"                                                        \
        "mbarrier.try_wait.parity.acquire.cta.shared::cta.b64 P1, [%0], %1, 0x989680;\n\t" \
        "@P1 bra.uni LAB_D_%=;\n\t"                                            \
        "bra.uni LAB_W_%=;\n\t"                                                \
        "LAB_D_%=:\n\t}"                                                       \
        :: "r"(addr), "r"(par) : "memory");                                    \
} while (0)

static __device__ __forceinline__ void ldsm4(U32& r0, U32& r1, U32& r2, U32& r3, U32 addr) {
    asm volatile("ldmatrix.sync.aligned.m8n8.x4.shared.b16 {%0,%1,%2,%3}, [%4];"
                 : "=r"(r0), "=r"(r1), "=r"(r2), "=r"(r3) : "r"(addr));
}

static __device__ __forceinline__ void mma16(float* c, U32 a0, U32 a1, U32 a2, U32 a3,
                                             U32 b0, U32 b1) {
    asm volatile("mma.sync.aligned.m16n8k16.row.col.f32.f16.f16.f32 "
                 "{%0,%1,%2,%3}, {%4,%5,%6,%7}, {%8,%9}, {%0,%1,%2,%3};"
                 : "+f"(c[0]), "+f"(c[1]), "+f"(c[2]), "+f"(c[3])
                 : "r"(a0), "r"(a1), "r"(a2), "r"(a3), "r"(b0), "r"(b1));
}

// pack (lo, hi) floats into one fp16x2 register
static __device__ __forceinline__ U32 cvt2h(float lo, float hi) {
    U32 r;
    asm("cvt.rn.f16x2.f32 %0, %1, %2;" : "=r"(r) : "f"(hi), "f"(lo));
    return r;
}

// ---------------- weight normalization + fp16 k-panel packing ----------------
// w' = (w - mean(w)) * rsqrt(sum((w-mean)^2)); dst: [kchunk][row][40 halves]
__global__ void normalize_kernel(const float* __restrict__ w) {
    int row  = blockIdx.x & (ODIM - 1);
    int half = blockIdx.x >> 7;
    const float* src = w + (size_t)row * (2 * IND) + (size_t)half * IND;
    __half* dst = half ? g_W1h : g_W0h;
    int t = threadIdx.x;  // 256 threads
    float v[4], s = 0.f, s2 = 0.f;
#pragma unroll
    for (int i = 0; i < 4; ++i) { v[i] = src[t + 256 * i]; s += v[i]; s2 += v[i] * v[i]; }
#pragma unroll
    for (int o = 16; o; o >>= 1) {
        s  += __shfl_xor_sync(~0u, s,  o);
        s2 += __shfl_xor_sync(~0u, s2, o);
    }
    __shared__ float sh[18];
    if ((t & 31) == 0) { sh[t >> 5] = s; sh[8 + (t >> 5)] = s2; }
    __syncthreads();
    if (t == 0) {
        float S = 0.f, S2 = 0.f;
#pragma unroll
        for (int i = 0; i < 8; ++i) { S += sh[i]; S2 += sh[8 + i]; }
        float mu = S * (1.f / IND);
        float ss = S2 - (float)IND * mu * mu;
        sh[16] = mu; sh[17] = rsqrtf(ss);
    }
    __syncthreads();
    float mu = sh[16], inv = sh[17];
#pragma unroll
    for (int i = 0; i < 4; ++i) {
        int k  = t + 256 * i;
        int kc = k >> 5, col = k & 31;
        dst[(size_t)kc * PANEL_H + row * PITCHH + col] = __float2half((v[i] - mu) * inv);
    }
    // zero pad cols 32..39
    {
        int kc = t >> 3, pc = 32 + (t & 7);
        dst[(size_t)kc * PANEL_H + row * PITCHH + pc] = __float2half(0.f);
    }
}

// ---------------- main fused GEMM (fp16 MMA, 2 CTAs/SM, single-sync) ----------------
// 8 warps: warps 0-3: out0 = x*W0^T, warps 4-7: out1 = y*W1^T. Warp tile 32x64.
// x/y: cp.async fp32 -> staging -> per-thread cvt -> fp16 slot. W: TMA fp16 panels.

static __device__ __forceinline__ void load_xy(U32 sb, int slot, int kchunk,
                                               const float* x, const float* y, int m0) {
    const int tid = threadIdx.x;
    const U32 sg = sb + SM_STG + slot * STG_BYTES;
    const int ch = tid & 7;          // 16B chunk within 128B row
    const int r0 = tid >> 3;         // base row 0..31
    const int kofs = kchunk * KC + ch * 4;
    const float* px = x + (size_t)(m0 + r0) * IND + kofs;
    const float* py = y + (size_t)(m0 + r0) * IND + kofs;
#pragma unroll
    for (int p = 0; p < 2; ++p) {
        const int row = r0 + 32 * p;
        const U32 so = (U32)(row * 128 + ch * 16);      // linear staging
        cp16(sg + so,        px + (size_t)(32 * p) * IND);
        cp16(sg + 8192 + so, py + (size_t)(32 * p) * IND);
    }
}

// each thread converts EXACTLY the bytes it staged (no cross-thread dependency)
static __device__ __forceinline__ void convert_xy(U32 sb, int stg_slot, int mma_slot) {
    const int tid = threadIdx.x;
    const U32 sg = sb + SM_STG  + stg_slot * STG_BYTES;
    const U32 sl = sb + SM_SLOT + mma_slot * SLOT_BYTES;
    const int ch = tid & 7;
    const int r0 = tid >> 3;
#pragma unroll
    for (int p = 0; p < 2; ++p) {
        const int row = r0 + 32 * p;
        const U32 so = (U32)(row * 128 + ch * 16);
        const U32 dof = (U32)(row * PITCHB + ch * 8);
        // x
        {
            float4 v;
            asm volatile("ld.shared.v4.f32 {%0,%1,%2,%3}, [%4];"
                         : "=f"(v.x), "=f"(v.y), "=f"(v.z), "=f"(v.w) : "r"(sg + so));
            U32 h0 = cvt2h(v.x, v.y), h1 = cvt2h(v.z, v.w);
            asm volatile("st.shared.v2.b32 [%0], {%1,%2};" :: "r"(sl + TO_X + dof), "r"(h0), "r"(h1));
        }
        // y
        {
            float4 v;
            asm volatile("ld.shared.v4.f32 {%0,%1,%2,%3}, [%4];"
                         : "=f"(v.x), "=f"(v.y), "=f"(v.z), "=f"(v.w) : "r"(sg + 8192 + so));
            U32 h0 = cvt2h(v.x, v.y), h1 = cvt2h(v.z, v.w);
            asm volatile("st.shared.v2.b32 [%0], {%1,%2};" :: "r"(sl + TO_Y + dof), "r"(h0), "r"(h1));
        }
    }
}

__global__ void __launch_bounds__(NTHR, 2)
gemm_kernel(const float* __restrict__ x, const float* __restrict__ y,
            const float* __restrict__ fc_bias, const float* __restrict__ a0,
            const float* __restrict__ a1, float* __restrict__ out) {
    extern __shared__ char smem[];
    const U32 sb = s2u(smem);
    const int tid = threadIdx.x;
    const int wid = tid >> 5, lid = tid & 31;
    const int m0 = blockIdx.x * BM;

    if (tid == 0) {
        mbar_init(sb + SM_MBAR + 0, 1);
        mbar_init(sb + SM_MBAR + 8, 1);
    }
    if (tid < 128) {
        float* sc = (float*)(smem + SM_COEF);
        sc[tid] = a0[tid]; sc[128 + tid] = a1[tid]; sc[256 + tid] = fc_bias[tid];
    }
    __syncthreads();

    // prologue: stage chunks 0,1 + W TMA for slots 0,1
    load_xy(sb, 0, 0, x, y, m0); cp_commit();
    load_xy(sb, 1, 1, x, y, m0); cp_commit();
    if (tid == 0) {
        mbar_expect(sb + SM_MBAR + 0, W_TX);
        bulk_g2s(sb + SM_SLOT + TO_W0, g_W0h, W_BYTES, sb + SM_MBAR + 0);
        bulk_g2s(sb + SM_SLOT + TO_W1, g_W1h, W_BYTES, sb + SM_MBAR + 0);
        mbar_expect(sb + SM_MBAR + 8, W_TX);
        bulk_g2s(sb + SM_SLOT + SLOT_BYTES + TO_W0, g_W0h + PANEL_H, W_BYTES, sb + SM_MBAR + 8);
        bulk_g2s(sb + SM_SLOT + SLOT_BYTES + TO_W1, g_W1h + PANEL_H, W_BYTES, sb + SM_MBAR + 8);
    }
    cp_wait<1>();                        // my chunk-0 staging landed
    convert_xy(sb, 0, 0);
    MBAR_WAIT(sb + SM_MBAR + 0, 0u);
    __syncthreads();                     // slot 0 fully ready

    // warp role
    const int g1 = wid >> 2;             // 0: GEMM0 (x,W0), 1: GEMM1 (y,W1)
    const int wl = wid & 3;
    const int mw = wl & 1;               // m-half (32 rows)
    const int nw = wl >> 1;              // n-half (64 cols)

    const int sel  = lid >> 3;
    const int lrow = lid & 7;
    const int aRowL = (sel & 1) * 8 + lrow;
    const U32 aKb   = (U32)((sel >> 1) * 16);    // k8-half within k16 (bytes)
    const int bRowL = sel * 8 + lrow;

    U32 aOff[2];
#pragma unroll
    for (int mt = 0; mt < 2; ++mt)
        aOff[mt] = (U32)((mw * 32 + mt * 16 + aRowL) * PITCHB) + aKb;
    U32 bOff[2];
#pragma unroll
    for (int g = 0; g < 2; ++g)
        bOff[g] = (U32)((nw * 64 + g * 32 + bRowL) * PITCHB);

    float acc[2][8][4];
#pragma unroll
    for (int mt = 0; mt < 2; ++mt)
#pragma unroll
        for (int nt = 0; nt < 8; ++nt)
#pragma unroll
            for (int q = 0; q < 4; ++q) acc[mt][nt][q] = 0.f;

    const U32 toA = g1 ? TO_Y : TO_X;
    const U32 toB = g1 ? TO_W1 : TO_W0;

    int ph0 = 1, ph1 = 0;
    for (int i = 0; i < NITER; ++i) {
        const int s = i & 1;
        if (i + 2 < NITER) load_xy(sb, s, i + 2, x, y, m0);
        cp_commit();

        const U32 st = sb + SM_SLOT + (U32)(s * SLOT_BYTES);
        const U32 abase = st + toA;
        const U32 bbase = st + toB;
#pragma unroll
        for (int ks = 0; ks < 2; ++ks) {       // 2 k16-steps per 32-elem chunk
            const U32 kb = (U32)(ks * 32);     // byte offset (32B = 16 fp16)
            U32 a[2][4];
#pragma unroll
            for (int mt = 0; mt < 2; ++mt)
                ldsm4(a[mt][0], a[mt][1], a[mt][2], a[mt][3], abase + aOff[mt] + kb);
#pragma unroll
            for (int g = 0; g < 2; ++g) {
                U32 b0[4], b1[4];
                ldsm4(b0[0], b0[1], b0[2], b0[3], bbase + bOff[g] + kb);
                ldsm4(b1[0], b1[1], b1[2], b1[3], bbase + bOff[g] + kb + 16u);
#pragma unroll
                for (int mt = 0; mt < 2; ++mt)
#pragma unroll
                    for (int j = 0; j < 4; ++j)
                        mma16(acc[mt][4 * g + j], a[mt][0], a[mt][1], a[mt][2], a[mt][3],
                              b0[j], b1[j]);
            }
        }

        if (i + 1 < NITER) {
            cp_wait<1>();                      // my staging(i+1) landed
            convert_xy(sb, s ^ 1, s ^ 1);      // own bytes only — no barrier needed
            if (s) { MBAR_WAIT(sb + SM_MBAR + 0, (U32)ph0); ph0 ^= 1; }
            else   { MBAR_WAIT(sb + SM_MBAR + 8, (U32)ph1); ph1 ^= 1; }
            __syncthreads();                   // all converts + W visible; slot s free
            if (i + 2 < NITER && tid == 0) {
                const U32 mb = sb + SM_MBAR + s * 8;
                mbar_expect(mb, W_TX);
                bulk_g2s(st + TO_W0, g_W0h + (size_t)(i + 2) * PANEL_H, W_BYTES, mb);
                bulk_g2s(st + TO_W1, g_W1h + (size_t)(i + 2) * PANEL_H, W_BYTES, mb);
            }
        }
    }
    __syncthreads();

    // ---------- epilogue ----------
    float* exch = (float*)(smem + SM_SLOT);    // reuse slot area: 64 x EXP fp32
    const float* sa0 = (const float*)(smem + SM_COEF);
    const float* sa1 = sa0 + 128;
    const float* sbs = sa0 + 256;

    const int rowb = mw * 32 + (lid >> 2);
    const int colb = nw * 64 + 2 * (lid & 3);

    if (!g1) {
#pragma unroll
        for (int mt = 0; mt < 2; ++mt) {
            const int rl = rowb + mt * 16;
#pragma unroll
            for (int nt = 0; nt < 8; ++nt) {
                const int c = colb + nt * 8;
                float2 v0 = make_float2(acc[mt][nt][0], acc[mt][nt][1]);
                float2 v1 = make_float2(acc[mt][nt][2], acc[mt][nt][3]);
                *(float2*)(out + (size_t)(m0 + rl)     * ODIM + c) = v0;
                *(float2*)(out + (size_t)(m0 + rl + 8) * ODIM + c) = v1;
                *(float2*)(exch + rl * EXP + c)       = v0;
                *(float2*)(exch + (rl + 8) * EXP + c) = v1;
            }
        }
    } else {
        float* o1 = out + (size_t)BATCHN * ODIM;
#pragma unroll
        for (int mt = 0; mt < 2; ++mt) {
            const int rl = rowb + mt * 16;
#pragma unroll
            for (int nt = 0; nt < 8; ++nt) {
                const int c = colb + nt * 8;
                *(float2*)(o1 + (size_t)(m0 + rl)     * ODIM + c) =
                    make_float2(acc[mt][nt][0], acc[mt][nt][1]);
                *(float2*)(o1 + (size_t)(m0 + rl + 8) * ODIM + c) =
                    make_float2(acc[mt][nt][2], acc[mt][nt][3]);
            }
        }
    }
    __syncthreads();

    if (g1) {
        float* o2 = out + 2 * (size_t)BATCHN * ODIM;
#pragma unroll
        for (int mt = 0; mt < 2; ++mt) {
            const int rl = rowb + mt * 16;
#pragma unroll
            for (int nt = 0; nt < 8; ++nt) {
                const int c = colb + nt * 8;
                float2 p0 = *(const float2*)(exch + rl * EXP + c);
                float2 p1 = *(const float2*)(exch + (rl + 8) * EXP + c);
                const float A0x = sa0[c], A0y = sa0[c + 1];
                const float A1x = sa1[c], A1y = sa1[c + 1];
                const float Bx  = sbs[c], By  = sbs[c + 1];
                float2 r0, r1;
                r0.x = p0.x * A0x + acc[mt][nt][0] * A1x + Bx;
                r0.y = p0.y * A0y + acc[mt][nt][1] * A1y + By;
                r1.x = p1.x * A0x + acc[mt][nt][2] * A1x + Bx;
                r1.y = p1.y * A0y + acc[mt][nt][3] * A1y + By;
                *(float2*)(o2 + (size_t)(m0 + rl)     * ODIM + c) = r0;
                *(float2*)(o2 + (size_t)(m0 + rl + 8) * ODIM + c) = r1;
            }
        }
    }
}

// ---------------- launch ----------------

extern "C" void kernel_launch(void* const* d_in, const int* in_sizes, int n_in,
                              void* d_out, int out_size) {
    const float* x  = (const float*)d_in[0];
    const float* y  = (const float*)d_in[1];
    const float* fw = (const float*)d_in[2];
    const float* fb = (const float*)d_in[3];
    const float* a0 = (const float*)d_in[4];
    const float* a1 = (const float*)d_in[5];
    float* out = (float*)d_out;

    normalize_kernel<<<2 * ODIM, 256>>>(fw);

    cudaFuncSetAttribute(gemm_kernel, cudaFuncAttributeMaxDynamicSharedMemorySize, SMEM_TOTAL);
    gemm_kernel<<<BATCHN / BM, NTHR, SMEM_TOTAL>>>(x, y, fb, a0, a1, out);
}